// round 9
// baseline (speedup 1.0000x reference)
#include <cuda_runtime.h>
#include <cuda_fp16.h>

#define B_     2
#define N_IN_  262144
#define D_     32
#define N_OUT_ 65536
#define K_     4
#define NK_    9
#define TOTAL_ (B_ * N_OUT_ * K_)   // 524288 outputs
#define NROWS_ (B_ * N_IN_)         // 524288 input rows

// Staged row, 128B stride, line-aligned:
// [ 32 x fp16 features (64B) | cx f32, cy f32 (8B) | 56B zero pad ]
__device__ uint4 g_xrow[NROWS_ * 8];   // 64 MB
__device__ float g_uc0;                // 1/(2*sigma^2) when uniform
__device__ int   g_u;                  // 1 = uniform, 2 = general

// ---------------- prep: 8 threads per row, one 16B slot each ----------------
// Warp covers 4 consecutive rows -> 512B contiguous stores (4 lines, coalesced).
__global__ void __launch_bounds__(256) prep_kernel(
    const float* __restrict__ x,      // (B, N_IN, D)
    const float* __restrict__ sigma,  // (D,)
    const float* __restrict__ cin)    // (2, B, N_IN)
{
    const int tid = blockIdx.x * blockDim.x + threadIdx.x;
    const int r   = tid >> 3;          // row
    const int s   = tid & 7;           // 16B slot within row

    if (blockIdx.x == 0 && threadIdx.x < 32) {
        float sv = sigma[threadIdx.x];
        float c = 1.0f / (2.0f * sv * sv);
        float c0 = __shfl_sync(0xffffffffu, c, 0);
        unsigned same = __ballot_sync(0xffffffffu, c == c0);
        if (threadIdx.x == 0) {
            g_u   = (same == 0xffffffffu) ? 1 : 2;
            g_uc0 = c0;
        }
    }

    uint4 v = make_uint4(0u, 0u, 0u, 0u);
    if (s < 4) {
        // slot s holds fp16 channels 8s..8s+7 = floats x[r][8s..8s+7]
        const float4* src = (const float4*)x + (size_t)r * 8 + s * 2;
        float4 a = __ldg(&src[0]);
        float4 bq = __ldg(&src[1]);
        __half2 h0 = __floats2half2_rn(a.x, a.y);
        __half2 h1 = __floats2half2_rn(a.z, a.w);
        __half2 h2 = __floats2half2_rn(bq.x, bq.y);
        __half2 h3 = __floats2half2_rn(bq.z, bq.w);
        v.x = *(const unsigned*)&h0;
        v.y = *(const unsigned*)&h1;
        v.z = *(const unsigned*)&h2;
        v.w = *(const unsigned*)&h3;
    } else if (s == 4) {
        v.x = __float_as_uint(__ldg(&cin[r]));
        v.y = __float_as_uint(__ldg(&cin[B_ * N_IN_ + r]));
    }
    g_xrow[tid] = v;
}

// ---------------- proj: warp = 4 outputs x 8 lanes ----------------
// m = 0..3 : 16B feature quad (8 fp16 channels) -> accumulate
// m = 4    : 16B coord quad (same LDG, same line) -> d2 + exp for all 9 j
// m = 5..7 : load 3 neighbor ints each
__global__ void __launch_bounds__(256) proj_kernel(
    const float* __restrict__ cout,   // (2, B, N_OUT, K)
    const float* __restrict__ sigma,  // (D,)
    const int*   __restrict__ nidx,   // (B, N_OUT, K, NK)
    float* __restrict__ out)          // (B, N_OUT*K, D)
{
    const unsigned lane = threadIdx.x & 31u;
    const int w    = (int)((blockIdx.x * (unsigned)blockDim.x + threadIdx.x) >> 5);
    const int bnk0 = w * 4;
    const int g    = (int)(lane >> 3);
    const int m    = (int)(lane & 7u);
    const int bnk  = bnk0 + g;
    const int b    = bnk0 >> 18;
    const unsigned gb = lane & 24u;    // group base lane

    // neighbor indices: lanes m=5,6,7 hold idx[m-5], idx[m-2], idx[m+1]
    int i0 = 0, i1 = 0, i2 = 0;
    if (m >= 5) {
        const size_t nb = (size_t)bnk * NK_ + (m - 5);
        i0 = __ldg(&nidx[nb]);
        i1 = __ldg(&nidx[nb + 3]);
        i2 = __ldg(&nidx[nb + 6]);
    }
    int ij[NK_];
#pragma unroll
    for (int j = 0; j < NK_; j++) {
        int v = (j < 3) ? i0 : (j < 6) ? i1 : i2;
        ij[j] = __shfl_sync(0xffffffffu, v, (int)(gb | (5u + (j % 3))));
    }

    // one gather instruction per neighbor covers features AND coords (one line)
    const uint4* base = g_xrow + (size_t)b * N_IN_ * 8 + m;
    uint4 f[NK_];
#pragma unroll
    for (int j = 0; j < NK_; j++) {
        if (m < 5) f[j] = __ldg(base + (size_t)ij[j] * 8);
        else       f[j] = make_uint4(0u, 0u, 0u, 0u);
    }

    // out-coords on lane m=4 only (coalesced-ish across groups)
    float ox = 0.0f, oy = 0.0f;
    if (m == 4) {
        ox = __ldg(&cout[bnk]);
        oy = __ldg(&cout[bnk + TOTAL_]);
    }

    if (g_u == 1) {
        // all 9 exponents hoisted before the accumulate loop (valid on m=4)
        const float cu = g_uc0;
        float e[NK_];
#pragma unroll
        for (int j = 0; j < NK_; j++) {
            float dx = ox - __uint_as_float(f[j].x);
            float dy = oy - __uint_as_float(f[j].y);
            e[j] = __expf(-(dx * dx + dy * dy) * cu);
        }

        float a0 = 0.f, a1 = 0.f, a2 = 0.f, a3 = 0.f;
        float a4 = 0.f, a5 = 0.f, a6 = 0.f, a7 = 0.f;
        float den = 1e-9f;
#pragma unroll
        for (int j = 0; j < NK_; j++) {
            float wj = __shfl_sync(0xffffffffu, e[j], (int)(gb | 4u));
            float2 p0 = __half22float2(*(const __half2*)&f[j].x);
            float2 p1 = __half22float2(*(const __half2*)&f[j].y);
            float2 p2 = __half22float2(*(const __half2*)&f[j].z);
            float2 p3 = __half22float2(*(const __half2*)&f[j].w);
            a0 = fmaf(wj, p0.x, a0);  a1 = fmaf(wj, p0.y, a1);
            a2 = fmaf(wj, p1.x, a2);  a3 = fmaf(wj, p1.y, a3);
            a4 = fmaf(wj, p2.x, a4);  a5 = fmaf(wj, p2.y, a5);
            a6 = fmaf(wj, p3.x, a6);  a7 = fmaf(wj, p3.y, a7);
            den += wj;
        }
        if (m < 4) {
            float inv = __fdividef(1.0f, den);
            float* dst = out + (size_t)bnk * D_ + m * 8;
            ((float4*)dst)[0] = make_float4(a0 * inv, a1 * inv, a2 * inv, a3 * inv);
            ((float4*)dst)[1] = make_float4(a4 * inv, a5 * inv, a6 * inv, a7 * inv);
        }
    } else {
        // general path: lane m=4 computes t[j], broadcast; each lane does
        // per-channel exps for its 8 channels (fallback, correctness-first)
        float t[NK_];
#pragma unroll
        for (int j = 0; j < NK_; j++) {
            float dx = ox - __uint_as_float(f[j].x);
            float dy = oy - __uint_as_float(f[j].y);
            t[j] = -(dx * dx + dy * dy);
        }
        float4 sa = ((const float4*)sigma)[m * 2 + 0];
        float4 sb = ((const float4*)sigma)[m * 2 + 1];   // m<4 valid; others unused
        float c0 = 1.0f / (2.0f * sa.x * sa.x);
        float c1 = 1.0f / (2.0f * sa.y * sa.y);
        float c2 = 1.0f / (2.0f * sa.z * sa.z);
        float c3 = 1.0f / (2.0f * sa.w * sa.w);
        float c4 = 1.0f / (2.0f * sb.x * sb.x);
        float c5 = 1.0f / (2.0f * sb.y * sb.y);
        float c6 = 1.0f / (2.0f * sb.z * sb.z);
        float c7 = 1.0f / (2.0f * sb.w * sb.w);
        float a0 = 0.f, a1 = 0.f, a2 = 0.f, a3 = 0.f;
        float a4 = 0.f, a5 = 0.f, a6 = 0.f, a7 = 0.f;
        float d0 = 1e-9f, d1 = 1e-9f, d2 = 1e-9f, d3 = 1e-9f;
        float d4 = 1e-9f, d5 = 1e-9f, d6 = 1e-9f, d7 = 1e-9f;
#pragma unroll
        for (int j = 0; j < NK_; j++) {
            float tv = __shfl_sync(0xffffffffu, t[j], (int)(gb | 4u));
            float w0 = __expf(tv * c0);
            float w1 = __expf(tv * c1);
            float w2 = __expf(tv * c2);
            float w3 = __expf(tv * c3);
            float w4 = __expf(tv * c4);
            float w5 = __expf(tv * c5);
            float w6 = __expf(tv * c6);
            float w7 = __expf(tv * c7);
            float2 p0 = __half22float2(*(const __half2*)&f[j].x);
            float2 p1 = __half22float2(*(const __half2*)&f[j].y);
            float2 p2 = __half22float2(*(const __half2*)&f[j].z);
            float2 p3 = __half22float2(*(const __half2*)&f[j].w);
            a0 = fmaf(w0, p0.x, a0);  a1 = fmaf(w1, p0.y, a1);
            a2 = fmaf(w2, p1.x, a2);  a3 = fmaf(w3, p1.y, a3);
            a4 = fmaf(w4, p2.x, a4);  a5 = fmaf(w5, p2.y, a5);
            a6 = fmaf(w6, p3.x, a6);  a7 = fmaf(w7, p3.y, a7);
            d0 += w0; d1 += w1; d2 += w2; d3 += w3;
            d4 += w4; d5 += w5; d6 += w6; d7 += w7;
        }
        if (m < 4) {
            float* dst = out + (size_t)bnk * D_ + m * 8;
            ((float4*)dst)[0] = make_float4(__fdividef(a0, d0), __fdividef(a1, d1),
                                            __fdividef(a2, d2), __fdividef(a3, d3));
            ((float4*)dst)[1] = make_float4(__fdividef(a4, d4), __fdividef(a5, d5),
                                            __fdividef(a6, d6), __fdividef(a7, d7));
        }
    }
}

extern "C" void kernel_launch(void* const* d_in, const int* in_sizes, int n_in,
                              void* d_out, int out_size) {
    const float* x     = (const float*)d_in[0];
    const float* cin   = (const float*)d_in[1];
    const float* cout  = (const float*)d_in[2];
    const float* sigma = (const float*)d_in[3];
    const int*   nidx  = (const int*)d_in[4];
    float* out = (float*)d_out;

    // staging: 8 threads/row -> 4,194,304 threads -> 16384 blocks
    prep_kernel<<<(NROWS_ * 8) / 256, 256>>>(x, sigma, cin);

    // proj: 4 outputs/warp -> 131072 warps -> 16384 blocks
    proj_kernel<<<TOTAL_ / 4 / 8, 256>>>(cout, sigma, nidx, out);
}

// round 10
// speedup vs baseline: 1.2910x; 1.2910x over previous
#include <cuda_runtime.h>
#include <cuda_fp16.h>

#define B_     2
#define N_IN_  262144
#define D_     32
#define N_OUT_ 65536
#define K_     4
#define NK_    9
#define TOTAL_ (B_ * N_OUT_ * K_)   // 524288 outputs

// sigma-dedup + interleaved coords + fp16 feature copy
__device__ float  g_uc0;                    // 1/(2*sigma^2) when uniform
__device__ int    g_u;                      // 1 = uniform sigma, 2 = general
__device__ float2 g_c2[B_ * N_IN_];         // (cx, cy) per input point
__device__ __half g_xh[B_ * N_IN_ * D_];    // fp16 features, 64B rows

// ---------------- prep (R4 version, measured 16.3 us) ----------------
__global__ void __launch_bounds__(256) prep_kernel(
    const float* __restrict__ x,
    const float* __restrict__ sigma,
    const float* __restrict__ cin)
{
    const int tid = blockIdx.x * blockDim.x + threadIdx.x;

    if (blockIdx.x == 0 && threadIdx.x < 32) {
        float s = sigma[threadIdx.x];
        float c = 1.0f / (2.0f * s * s);
        float c0 = __shfl_sync(0xffffffffu, c, 0);
        unsigned same = __ballot_sync(0xffffffffu, c == c0);
        if (threadIdx.x == 0) {
            g_u   = (same == 0xffffffffu) ? 1 : 2;
            g_uc0 = c0;
        }
    }

    {
        const float4* x4 = (const float4*)x;
        float4 a = __ldg(&x4[tid * 2]);
        float4 bq = __ldg(&x4[tid * 2 + 1]);
        __half2 h0 = __floats2half2_rn(a.x, a.y);
        __half2 h1 = __floats2half2_rn(a.z, a.w);
        __half2 h2 = __floats2half2_rn(bq.x, bq.y);
        __half2 h3 = __floats2half2_rn(bq.z, bq.w);
        uint4 p;
        p.x = *(const unsigned*)&h0;
        p.y = *(const unsigned*)&h1;
        p.z = *(const unsigned*)&h2;
        p.w = *(const unsigned*)&h3;
        ((uint4*)g_xh)[tid] = p;
    }

    if (tid < (B_ * N_IN_) / 4) {
        float4 cx = __ldg(&((const float4*)cin)[tid]);
        float4 cy = __ldg(&((const float4*)(cin + B_ * N_IN_))[tid]);
        float4* dst = (float4*)g_c2;
        dst[tid * 2 + 0] = make_float4(cx.x, cy.x, cx.y, cy.y);
        dst[tid * 2 + 1] = make_float4(cx.z, cy.z, cx.w, cy.w);
    }
}

// ---------------- uniform-sigma hot kernel (R4 layout, lean) ----------------
// Warp = 4 outputs. lane: g = lane>>3 (output), sl = lane&7 (channels 4sl..4sl+3).
__global__ void __launch_bounds__(256) proj_uniform_kernel(
    const float* __restrict__ cout,   // (2, B, N_OUT, K)
    const int*   __restrict__ nidx,   // (B, N_OUT, K, NK)
    float* __restrict__ out)          // (B, N_OUT*K, D)
{
    if (g_u != 1) return;

    const unsigned lane = threadIdx.x & 31u;
    const int w    = (int)((blockIdx.x * (unsigned)blockDim.x + threadIdx.x) >> 5);
    const int bnk0 = w * 4;
    const int g    = (int)(lane >> 3);
    const int sl   = (int)(lane & 7u);
    const int bnk  = bnk0 + g;
    const int b    = bnk0 >> 18;

    // lanes 0..17: (output o, neighbor j) for phase A (outputs 0,1) / B (2,3)
    int   idxA = 0, idxB = 0;
    float tA = 0.0f, tB = 0.0f;
    if (lane < 2 * NK_) {
        const int o = (lane >= NK_) ? 1 : 0;
        const int j = (int)lane - o * NK_;
        const int oA = bnk0 + o;
        idxA = __ldg(&nidx[(size_t)oA * NK_ + j]);
        const int oB = bnk0 + 2 + o;
        idxB = __ldg(&nidx[(size_t)oB * NK_ + j]);
        float2 cA = g_c2[b * N_IN_ + idxA];
        float2 cB = g_c2[b * N_IN_ + idxB];
        float oxA = __ldg(&cout[oA]);
        float oyA = __ldg(&cout[oA + TOTAL_]);
        float oxB = __ldg(&cout[oB]);
        float oyB = __ldg(&cout[oB + TOTAL_]);
        float dxA = oxA - cA.x, dyA = oyA - cA.y;
        float dxB = oxB - cB.x, dyB = oyB - cB.y;
        tA = -(dxA * dxA + dyA * dyA);
        tB = -(dxB * dxB + dyB * dyB);
    }

    // fused idx-broadcast + gather (frees the ij[] array; loads stay batched)
    const int selbase = (g & 1) * NK_;
    const uint2* xb = (const uint2*)g_xh + (size_t)b * N_IN_ * (D_ / 4) + sl;
    uint2 f[NK_];
#pragma unroll
    for (int j = 0; j < NK_; j++) {
        int a  = __shfl_sync(0xffffffffu, idxA, selbase + j);
        int bb = __shfl_sync(0xffffffffu, idxB, selbase + j);
        int ix = (g < 2) ? a : bb;
        f[j] = __ldg(xb + (size_t)ix * (D_ / 4));
    }

    // 2 MUFU passes warp-wide cover all 36 weights
    float eA = __expf(tA * g_uc0);
    float eB = __expf(tB * g_uc0);

    float4 num = make_float4(0.f, 0.f, 0.f, 0.f);
    float den = 1e-9f;
#pragma unroll
    for (int j = 0; j < NK_; j++) {
        float ea = __shfl_sync(0xffffffffu, eA, selbase + j);
        float eb = __shfl_sync(0xffffffffu, eB, selbase + j);
        float wj = (g < 2) ? ea : eb;
        float2 lo = __half22float2(*(const __half2*)&f[j].x);
        float2 hi = __half22float2(*(const __half2*)&f[j].y);
        num.x = fmaf(wj, lo.x, num.x);
        num.y = fmaf(wj, lo.y, num.y);
        num.z = fmaf(wj, hi.x, num.z);
        num.w = fmaf(wj, hi.y, num.w);
        den += wj;
    }
    float inv = __fdividef(1.0f, den);
    float4 r = make_float4(num.x * inv, num.y * inv, num.z * inv, num.w * inv);
    ((float4*)(out + (size_t)bnk * D_))[sl] = r;
}

// ---------------- general-sigma fallback (dead unless sigma varies) --------
__global__ void __launch_bounds__(256) proj_general_kernel(
    const float* __restrict__ cout,
    const float* __restrict__ sigma,
    const int*   __restrict__ nidx,
    float* __restrict__ out)
{
    if (g_u == 1) return;

    const unsigned lane = threadIdx.x & 31u;
    const int w    = (int)((blockIdx.x * (unsigned)blockDim.x + threadIdx.x) >> 5);
    const int bnk0 = w * 4;
    const int g    = (int)(lane >> 3);
    const int sl   = (int)(lane & 7u);
    const int bnk  = bnk0 + g;
    const int b    = bnk0 >> 18;

    int   idxA = 0, idxB = 0;
    float tA = 0.0f, tB = 0.0f;
    if (lane < 2 * NK_) {
        const int o = (lane >= NK_) ? 1 : 0;
        const int j = (int)lane - o * NK_;
        const int oA = bnk0 + o;
        idxA = __ldg(&nidx[(size_t)oA * NK_ + j]);
        const int oB = bnk0 + 2 + o;
        idxB = __ldg(&nidx[(size_t)oB * NK_ + j]);
        float2 cA = g_c2[b * N_IN_ + idxA];
        float2 cB = g_c2[b * N_IN_ + idxB];
        float oxA = __ldg(&cout[oA]);
        float oyA = __ldg(&cout[oA + TOTAL_]);
        float oxB = __ldg(&cout[oB]);
        float oyB = __ldg(&cout[oB + TOTAL_]);
        float dxA = oxA - cA.x, dyA = oyA - cA.y;
        float dxB = oxB - cB.x, dyB = oyB - cB.y;
        tA = -(dxA * dxA + dyA * dyA);
        tB = -(dxB * dxB + dyB * dyB);
    }

    const int selbase = (g & 1) * NK_;
    const uint2* xb = (const uint2*)g_xh + (size_t)b * N_IN_ * (D_ / 4) + sl;
    uint2 f[NK_];
#pragma unroll
    for (int j = 0; j < NK_; j++) {
        int a  = __shfl_sync(0xffffffffu, idxA, selbase + j);
        int bb = __shfl_sync(0xffffffffu, idxB, selbase + j);
        int ix = (g < 2) ? a : bb;
        f[j] = __ldg(xb + (size_t)ix * (D_ / 4));
    }

    float4 s4 = ((const float4*)sigma)[sl];
    float c0 = 1.0f / (2.0f * s4.x * s4.x);
    float c1 = 1.0f / (2.0f * s4.y * s4.y);
    float c2 = 1.0f / (2.0f * s4.z * s4.z);
    float c3 = 1.0f / (2.0f * s4.w * s4.w);
    float4 num = make_float4(0.f, 0.f, 0.f, 0.f);
    float d0 = 1e-9f, d1 = 1e-9f, d2 = 1e-9f, d3 = 1e-9f;
#pragma unroll
    for (int j = 0; j < NK_; j++) {
        float ta = __shfl_sync(0xffffffffu, tA, selbase + j);
        float tb = __shfl_sync(0xffffffffu, tB, selbase + j);
        float tv = (g < 2) ? ta : tb;
        float w0 = __expf(tv * c0);
        float w1 = __expf(tv * c1);
        float w2 = __expf(tv * c2);
        float w3 = __expf(tv * c3);
        float2 lo = __half22float2(*(const __half2*)&f[j].x);
        float2 hi = __half22float2(*(const __half2*)&f[j].y);
        num.x = fmaf(w0, lo.x, num.x);
        num.y = fmaf(w1, lo.y, num.y);
        num.z = fmaf(w2, hi.x, num.z);
        num.w = fmaf(w3, hi.y, num.w);
        d0 += w0; d1 += w1; d2 += w2; d3 += w3;
    }
    float4 r = make_float4(__fdividef(num.x, d0), __fdividef(num.y, d1),
                           __fdividef(num.z, d2), __fdividef(num.w, d3));
    ((float4*)(out + (size_t)bnk * D_))[sl] = r;
}

extern "C" void kernel_launch(void* const* d_in, const int* in_sizes, int n_in,
                              void* d_out, int out_size) {
    const float* x     = (const float*)d_in[0];
    const float* cin   = (const float*)d_in[1];
    const float* cout  = (const float*)d_in[2];
    const float* sigma = (const float*)d_in[3];
    const int*   nidx  = (const int*)d_in[4];
    float* out = (float*)d_out;

    prep_kernel<<<(B_ * N_IN_ * D_) / 8 / 256, 256>>>(x, sigma, cin);

    const int blocks = TOTAL_ / 4 / 8;   // 16384
    proj_uniform_kernel<<<blocks, 256>>>(cout, nidx, out);
    proj_general_kernel<<<blocks, 256>>>(cout, sigma, nidx, out);
}

// round 11
// speedup vs baseline: 1.4055x; 1.0887x over previous
#include <cuda_runtime.h>
#include <cuda_fp16.h>

#define B_     2
#define N_IN_  262144
#define D_     32
#define N_OUT_ 65536
#define K_     4
#define NK_    9
#define TOTAL_ (B_ * N_OUT_ * K_)   // 524288 outputs

// sigma-dedup + interleaved coords + fp16 feature copy
__device__ float  g_uc0;                    // 1/(2*sigma^2) when uniform
__device__ int    g_u;                      // 1 = uniform sigma, 2 = general
__device__ float2 g_c2[B_ * N_IN_];         // (cx, cy) per input point
__device__ __half g_xh[B_ * N_IN_ * D_];    // fp16 features, 64B rows

// ---------------- prep (R4 version, measured ~15.6 us) ----------------
__global__ void __launch_bounds__(256) prep_kernel(
    const float* __restrict__ x,
    const float* __restrict__ sigma,
    const float* __restrict__ cin)
{
    const int tid = blockIdx.x * blockDim.x + threadIdx.x;

    if (blockIdx.x == 0 && threadIdx.x < 32) {
        float s = sigma[threadIdx.x];
        float c = 1.0f / (2.0f * s * s);
        float c0 = __shfl_sync(0xffffffffu, c, 0);
        unsigned same = __ballot_sync(0xffffffffu, c == c0);
        if (threadIdx.x == 0) {
            g_u   = (same == 0xffffffffu) ? 1 : 2;
            g_uc0 = c0;
        }
    }

    {
        const float4* x4 = (const float4*)x;
        float4 a = __ldg(&x4[tid * 2]);
        float4 bq = __ldg(&x4[tid * 2 + 1]);
        __half2 h0 = __floats2half2_rn(a.x, a.y);
        __half2 h1 = __floats2half2_rn(a.z, a.w);
        __half2 h2 = __floats2half2_rn(bq.x, bq.y);
        __half2 h3 = __floats2half2_rn(bq.z, bq.w);
        uint4 p;
        p.x = *(const unsigned*)&h0;
        p.y = *(const unsigned*)&h1;
        p.z = *(const unsigned*)&h2;
        p.w = *(const unsigned*)&h3;
        ((uint4*)g_xh)[tid] = p;
    }

    if (tid < (B_ * N_IN_) / 4) {
        float4 cx = __ldg(&((const float4*)cin)[tid]);
        float4 cy = __ldg(&((const float4*)(cin + B_ * N_IN_))[tid]);
        float4* dst = (float4*)g_c2;
        dst[tid * 2 + 0] = make_float4(cx.x, cy.x, cx.y, cy.y);
        dst[tid * 2 + 1] = make_float4(cx.z, cy.z, cx.w, cy.w);
    }
}

// ---------------- uniform-sigma hot kernel: R4 proj body verbatim ----------
// Warp = 4 outputs. lane: g = lane>>3 (output), sl = lane&7 (channels 4sl..4sl+3).
__global__ void __launch_bounds__(256) proj_uniform_kernel(
    const float* __restrict__ cout,   // (2, B, N_OUT, K)
    const int*   __restrict__ nidx,   // (B, N_OUT, K, NK)
    float* __restrict__ out)          // (B, N_OUT*K, D)
{
    if (g_u != 1) return;

    const unsigned lane = threadIdx.x & 31u;
    const int w    = (int)((blockIdx.x * (unsigned)blockDim.x + threadIdx.x) >> 5);
    const int bnk0 = w * 4;
    const int g    = (int)(lane >> 3);
    const int sl   = (int)(lane & 7u);
    const int bnk  = bnk0 + g;
    const int b    = bnk0 >> 18;

    // lanes 0..17: (output o, neighbor j), phase A (outputs 0,1) / B (2,3)
    int   idxA = 0, idxB = 0;
    float tA = 0.0f, tB = 0.0f;
    if (lane < 2 * NK_) {
        const int o = (lane >= NK_) ? 1 : 0;
        const int j = (int)lane - o * NK_;
        const int oA = bnk0 + o;
        idxA = __ldg(&nidx[(size_t)oA * NK_ + j]);
        const int oB = bnk0 + 2 + o;
        idxB = __ldg(&nidx[(size_t)oB * NK_ + j]);
        float2 cA = g_c2[b * N_IN_ + idxA];
        float2 cB = g_c2[b * N_IN_ + idxB];
        float oxA = __ldg(&cout[oA]);
        float oyA = __ldg(&cout[oA + TOTAL_]);
        float oxB = __ldg(&cout[oB]);
        float oyB = __ldg(&cout[oB + TOTAL_]);
        float dxA = oxA - cA.x, dyA = oyA - cA.y;
        float dxB = oxB - cB.x, dyB = oyB - cB.y;
        tA = -(dxA * dxA + dyA * dyA);
        tB = -(dxB * dxB + dyB * dyB);
    }

    // idx broadcast FIRST (separate loop), then batched gathers (MLP = 9)
    const int selbase = (g & 1) * NK_;
    int ij[NK_];
#pragma unroll
    for (int j = 0; j < NK_; j++) {
        int a  = __shfl_sync(0xffffffffu, idxA, selbase + j);
        int bb = __shfl_sync(0xffffffffu, idxB, selbase + j);
        ij[j] = (g < 2) ? a : bb;
    }

    const uint2* xb = (const uint2*)g_xh + (size_t)b * N_IN_ * (D_ / 4) + sl;
    uint2 f[NK_];
#pragma unroll
    for (int j = 0; j < NK_; j++) f[j] = __ldg(xb + (size_t)ij[j] * (D_ / 4));

    // 2 MUFU passes warp-wide cover all 36 weights
    float eA = __expf(tA * g_uc0);
    float eB = __expf(tB * g_uc0);

    float4 num = make_float4(0.f, 0.f, 0.f, 0.f);
    float den = 1e-9f;
#pragma unroll
    for (int j = 0; j < NK_; j++) {
        float ea = __shfl_sync(0xffffffffu, eA, selbase + j);
        float eb = __shfl_sync(0xffffffffu, eB, selbase + j);
        float wj = (g < 2) ? ea : eb;
        float2 lo = __half22float2(*(const __half2*)&f[j].x);
        float2 hi = __half22float2(*(const __half2*)&f[j].y);
        num.x = fmaf(wj, lo.x, num.x);
        num.y = fmaf(wj, lo.y, num.y);
        num.z = fmaf(wj, hi.x, num.z);
        num.w = fmaf(wj, hi.y, num.w);
        den += wj;
    }
    float inv = __fdividef(1.0f, den);
    float4 r = make_float4(num.x * inv, num.y * inv, num.z * inv, num.w * inv);
    ((float4*)(out + (size_t)bnk * D_))[sl] = r;
}

// ---------------- general-sigma fallback: grid-strided, dead-cheap ---------
__global__ void __launch_bounds__(256) proj_general_kernel(
    const float* __restrict__ cout,
    const float* __restrict__ sigma,
    const int*   __restrict__ nidx,
    float* __restrict__ out)
{
    if (g_u == 1) return;

    const unsigned lane = threadIdx.x & 31u;
    const int nwarps_total = TOTAL_ / 4;   // 131072 warp-units
    const int warps_per_grid = (int)((gridDim.x * blockDim.x) >> 5);

    for (int w = (int)((blockIdx.x * (unsigned)blockDim.x + threadIdx.x) >> 5);
         w < nwarps_total; w += warps_per_grid) {
        const int bnk0 = w * 4;
        const int g    = (int)(lane >> 3);
        const int sl   = (int)(lane & 7u);
        const int bnk  = bnk0 + g;
        const int b    = bnk0 >> 18;

        int   idxA = 0, idxB = 0;
        float tA = 0.0f, tB = 0.0f;
        if (lane < 2 * NK_) {
            const int o = (lane >= NK_) ? 1 : 0;
            const int j = (int)lane - o * NK_;
            const int oA = bnk0 + o;
            idxA = __ldg(&nidx[(size_t)oA * NK_ + j]);
            const int oB = bnk0 + 2 + o;
            idxB = __ldg(&nidx[(size_t)oB * NK_ + j]);
            float2 cA = g_c2[b * N_IN_ + idxA];
            float2 cB = g_c2[b * N_IN_ + idxB];
            float oxA = __ldg(&cout[oA]);
            float oyA = __ldg(&cout[oA + TOTAL_]);
            float oxB = __ldg(&cout[oB]);
            float oyB = __ldg(&cout[oB + TOTAL_]);
            float dxA = oxA - cA.x, dyA = oyA - cA.y;
            float dxB = oxB - cB.x, dyB = oyB - cB.y;
            tA = -(dxA * dxA + dyA * dyA);
            tB = -(dxB * dxB + dyB * dyB);
        }

        const int selbase = (g & 1) * NK_;
        int ij[NK_];
#pragma unroll
        for (int j = 0; j < NK_; j++) {
            int a  = __shfl_sync(0xffffffffu, idxA, selbase + j);
            int bb = __shfl_sync(0xffffffffu, idxB, selbase + j);
            ij[j] = (g < 2) ? a : bb;
        }

        const uint2* xb = (const uint2*)g_xh + (size_t)b * N_IN_ * (D_ / 4) + sl;
        uint2 f[NK_];
#pragma unroll
        for (int j = 0; j < NK_; j++) f[j] = __ldg(xb + (size_t)ij[j] * (D_ / 4));

        float4 s4 = ((const float4*)sigma)[sl];
        float c0 = 1.0f / (2.0f * s4.x * s4.x);
        float c1 = 1.0f / (2.0f * s4.y * s4.y);
        float c2 = 1.0f / (2.0f * s4.z * s4.z);
        float c3 = 1.0f / (2.0f * s4.w * s4.w);
        float4 num = make_float4(0.f, 0.f, 0.f, 0.f);
        float d0 = 1e-9f, d1 = 1e-9f, d2 = 1e-9f, d3 = 1e-9f;
#pragma unroll
        for (int j = 0; j < NK_; j++) {
            float ta = __shfl_sync(0xffffffffu, tA, selbase + j);
            float tb = __shfl_sync(0xffffffffu, tB, selbase + j);
            float tv = (g < 2) ? ta : tb;
            float w0 = __expf(tv * c0);
            float w1 = __expf(tv * c1);
            float w2 = __expf(tv * c2);
            float w3 = __expf(tv * c3);
            float2 lo = __half22float2(*(const __half2*)&f[j].x);
            float2 hi = __half22float2(*(const __half2*)&f[j].y);
            num.x = fmaf(w0, lo.x, num.x);
            num.y = fmaf(w1, lo.y, num.y);
            num.z = fmaf(w2, hi.x, num.z);
            num.w = fmaf(w3, hi.y, num.w);
            d0 += w0; d1 += w1; d2 += w2; d3 += w3;
        }
        float4 r = make_float4(__fdividef(num.x, d0), __fdividef(num.y, d1),
                               __fdividef(num.z, d2), __fdividef(num.w, d3));
        ((float4*)(out + (size_t)bnk * D_))[sl] = r;
    }
}

extern "C" void kernel_launch(void* const* d_in, const int* in_sizes, int n_in,
                              void* d_out, int out_size) {
    const float* x     = (const float*)d_in[0];
    const float* cin   = (const float*)d_in[1];
    const float* cout  = (const float*)d_in[2];
    const float* sigma = (const float*)d_in[3];
    const int*   nidx  = (const int*)d_in[4];
    float* out = (float*)d_out;

    prep_kernel<<<(B_ * N_IN_ * D_) / 8 / 256, 256>>>(x, sigma, cin);

    // hot path: 4 outputs/warp -> 131072 warps -> 16384 blocks
    proj_uniform_kernel<<<TOTAL_ / 4 / 8, 256>>>(cout, nidx, out);
    // fallback: grid-strided over all outputs, tiny dead cost when uniform
    proj_general_kernel<<<1184, 256>>>(cout, sigma, nidx, out);
}